// round 17
// baseline (speedup 1.0000x reference)
#include <cuda_runtime.h>

#define XSIZE 256
#define ROUNDS 8
#define PPR 64          // patches produced/consumed per block-round

// Block = 128 threads: warps 0-1 = producers (MUFU: phase sincos),
// warps 2-3 = consumers (FMA: butterflies + readout). Double-buffered smem
// hands off 32 phase floats per patch. Both pipes run concurrently because
// they are driven by DIFFERENT warps — no scheduler cooperation required.
__global__ __launch_bounds__(128) void qconv_ws(const float* __restrict__ x,
                                                const float* __restrict__ w,
                                                float* __restrict__ out)
{
    __shared__ float sh[5];                 // tau0..3, scale
    __shared__ float4 buf[2][8][PPR];       // [buffer][e][patch slot]

    if (threadIdx.x == 0) {
        float C = 1.0f;
#pragma unroll
        for (int q = 0; q < 4; q++) {
            float cq, sq;
            __sincosf(0.5f * __ldg(w + q), &sq, &cq);
            sh[q] = __fdividef(sq, cq);     // tan(w_q/2)
            C *= cq;
        }
        sh[4] = 0.0625f * C * C;            // prod cos^2 folded into prob scale
    }
    __syncthreads();

    const int tid  = threadIdx.x;
    const int warp = tid >> 5;
    const int slot = tid & 63;              // patch slot 0..63 within the round
    const int pb   = blockIdx.x * (ROUNDS * PPR);

    const float u0 = sh[0], u1 = sh[1], u2 = sh[2], u3 = sh[3];
    const float scale = sh[4];

    for (int r = 0; r <= ROUNDS; r++) {
        if (warp < 2) {
            // ── producer: phases of round r
            if (r < ROUNDS) {
                const int p   = pb + r * PPR + slot;
                const int img = p >> 14;
                const int rem = p & 16383;
                const int pi  = rem >> 7;
                const int pj  = rem & 127;
                const size_t base = ((size_t)img * XSIZE + 2 * pi) * XSIZE + 2 * pj;
                const float2 q0 = *reinterpret_cast<const float2*>(x + base);
                const float2 q1 = *reinterpret_cast<const float2*>(x + base + XSIZE);
                const float y0 = 0.5f * q0.x, y1 = 0.5f * q0.y;
                const float y2 = 0.5f * q1.x, y3 = 0.5f * q1.y;
                const float ap = y3 + y2, am = y3 - y2;
                const float bp = y1 + y0, bm = y1 - y0;
#pragma unroll
                for (int e = 0; e < 8; e++) {
                    // h_e = (e&4? ap:am) ± {bp,bm}; phi = -h^2 ∓ h
                    const float he = ((e & 4) ? ap : am) +
                        ((e & 3) == 0 ? -bp : (e & 3) == 1 ? -bm
                         : (e & 3) == 2 ?  bm :  bp);
                    const float p1 = __fmaf_rn(he, -he, -he);
                    const float p0 = __fmaf_rn(he, -he,  he);
                    float s1, c1, s0, c0;
                    __sincosf(p1, &s1, &c1);
                    __sincosf(p0, &s0, &c0);
                    buf[r & 1][e][slot] = make_float4(s1, c1, s0, c0);
                }
            }
        } else {
            // ── consumer: butterflies + readout of round r-1
            if (r > 0) {
                const int rc  = r - 1;
                const int p   = pb + rc * PPR + slot;
                const int img = p >> 14;
                const int rem = p & 16383;
                const int pi  = rem >> 7;
                const int pj  = rem & 127;

                float vr[16], vi[16];
#pragma unroll
                for (int e = 0; e < 8; e++) {
                    const float4 f = buf[rc & 1][e][slot];
                    vi[8 | e] = f.x;  vr[8 | e] = f.y;
                    vi[e ^ 7] = f.z;  vr[e ^ 7] = f.w;
                }

                const float tau[4] = {u0, u1, u2, u3};
#pragma unroll
                for (int q = 0; q < 4; q++) {
                    const float tq = tau[q];
#pragma unroll
                    for (int m = 0; m < 8; m++) {
                        const int j0 = ((m >> q) << (q + 1)) | (m & ((1 << q) - 1));
                        const int j1 = j0 | (1 << q);
                        const float ar = vr[j0], ai = vi[j0];
                        const float br = vr[j1], bim = vi[j1];
                        vr[j0] = __fmaf_rn( tq, bim, ar);
                        vi[j0] = __fmaf_rn(-tq, br,  ai);
                        vr[j1] = __fmaf_rn( tq, ai,  br);
                        vi[j1] = __fmaf_rn(-tq, ar,  bim);
                    }
                }

                float o0 = 0.f, o1 = 0.f, o2 = 0.f, o3 = 0.f;
#pragma unroll
                for (int k = 0; k < 16; k++) {
                    const float pk_ = __fmaf_rn(vr[k], vr[k], vi[k] * vi[k]);
                    if (__popc(k & 0xF) & 1) o0 += pk_;
                    if (__popc(k & 0x7) & 1) o1 += pk_;
                    if (__popc(k & 0x3) & 1) o2 += pk_;
                    if (__popc(k & 0xE) & 1) o3 += pk_;
                }

                float4 o;
                o.x = scale * o0;
                o.y = scale * o1;
                o.z = scale * o2;
                o.w = scale * o3;
                reinterpret_cast<float4*>(out)[((size_t)img * 128 + pi) * 128 + pj] = o;
            }
        }
        __syncthreads();
    }
}

extern "C" void kernel_launch(void* const* d_in, const int* in_sizes, int n_in,
                              void* d_out, int out_size)
{
    const float* x = (const float*)d_in[0];
    const float* w = (const float*)d_in[1];
    float* out = (float*)d_out;
    const int batch  = in_sizes[0] / (XSIZE * XSIZE);
    const int blocks = batch * 16384 / (ROUNDS * PPR);   // 64 -> 2048 blocks
    qconv_ws<<<blocks, 128>>>(x, w, out);
}